// round 5
// baseline (speedup 1.0000x reference)
#include <cuda_runtime.h>
#include <math.h>
#include <stdint.h>

// Problem constants
#define Bv 2
#define Tv 8
#define Nv 576
#define Cv 1024
#define Hv 16
#define HDv 64
#define TNv (Tv * Nv)       // 4608
#define Mrows (Bv * TNv)    // 9216

// Scratch (device globals — no runtime allocation allowed)
__device__ float g_q[(size_t)Mrows * Cv];
__device__ float g_k[(size_t)Mrows * Cv];
__device__ float g_v[(size_t)Mrows * Cv];
__device__ float g_o[(size_t)Mrows * Cv];

// ---------------------------------------------------------------------------
// tf32 helpers
// ---------------------------------------------------------------------------
__device__ __forceinline__ unsigned tf32r(float x) {
    unsigned r;
    asm("cvt.rna.tf32.f32 %0, %1;" : "=r"(r) : "f"(x));
    return r;
}

__device__ __forceinline__ void mma8(float d[4], const unsigned a[4],
                                     const unsigned b[2]) {
    asm volatile(
        "mma.sync.aligned.m16n8k8.row.col.f32.tf32.tf32.f32 "
        "{%0,%1,%2,%3},{%4,%5,%6,%7},{%8,%9},{%0,%1,%2,%3};"
        : "+f"(d[0]), "+f"(d[1]), "+f"(d[2]), "+f"(d[3])
        : "r"(a[0]), "r"(a[1]), "r"(a[2]), "r"(a[3]), "r"(b[0]), "r"(b[1]));
}

__device__ __forceinline__ float fcomp(const float4& v, int g) {
    switch (g & 3) {
        case 0:  return v.x;
        case 1:  return v.y;
        case 2:  return v.z;
        default: return v.w;
    }
}

// ---------------------------------------------------------------------------
// NT GEMM via tf32 mma, fragment-major smem layout.
// C[m,n] = sum_k A[m,k] * W[n,k] (+ bias[n])
// Block 128x128, BK=16, 8 warps (2m x 4n), warp tile 64x32.
//
// Smem chunk layout: per row m (128 rows, stride 16 words), 4 16B groups.
// Physical group p = (g + m + (m>>2)) & 3 holds logical group g =
// {k: k mod 4 == g}, in order k = g, g+4, g+8, g+12.
// One LDS.128 per row yields the thread's a0/a2 (or b0/b1) for BOTH
// 8-k sub-steps. Stores (per logical g across rows) and loads (per row
// pair) are both shared-memory conflict-free (verified by enumeration).
// ---------------------------------------------------------------------------
__global__ __launch_bounds__(256) void gemm_tf32(
    const float* __restrict__ A, const float* __restrict__ W,
    float* __restrict__ Cout, const float* __restrict__ bias)
{
    __shared__ unsigned As[2][128 * 16];
    __shared__ unsigned Bs[2][128 * 16];

    const int t = threadIdx.x;
    const int lane = t & 31;
    const int w = t >> 5;
    const int gid = lane >> 2, tig = lane & 3;
    const int wm = (w >> 2) * 64, wn = (w & 3) * 32;
    const int m0 = blockIdx.y * 128, n0 = blockIdx.x * 128;

    // Loader role: threads 0-127 -> A row lm, threads 128-255 -> B row lm
    const int lm = t & 127;
    const bool isA = t < 128;
    const float* src = isA ? (A + (size_t)(m0 + lm) * Cv)
                           : (W + (size_t)(n0 + lm) * Cv);
    const int lph = lm + (lm >> 2);   // permutation base for this row

    float acc[4][4][4];
#pragma unroll
    for (int mt = 0; mt < 4; mt++)
#pragma unroll
        for (int nt = 0; nt < 4; nt++)
#pragma unroll
            for (int r = 0; r < 4; r++) acc[mt][nt][r] = 0.0f;

    float4 v[4];
#pragma unroll
    for (int c = 0; c < 4; c++) v[c] = *(const float4*)(src + c * 4);

    // store chunk regs -> smem buffer buf
    auto store_chunk = [&](int buf) {
        unsigned* dst = (isA ? As[buf] : Bs[buf]) + lm * 16;
#pragma unroll
        for (int g = 0; g < 4; g++) {
            const int p = (g + lph) & 3;
            uint4 o;
            o.x = tf32r(fcomp(v[0], g));
            o.y = tf32r(fcomp(v[1], g));
            o.z = tf32r(fcomp(v[2], g));
            o.w = tf32r(fcomp(v[3], g));
            *(uint4*)(dst + p * 4) = o;
        }
    };

    store_chunk(0);

    for (int ch = 0; ch < 64; ch++) {
        __syncthreads();
        const int buf = ch & 1;
        if (ch + 1 < 64) {
            const float* s2 = src + (ch + 1) * 16;
#pragma unroll
            for (int c = 0; c < 4; c++) v[c] = *(const float4*)(s2 + c * 4);
        }

        // fragment loads: one LDS.128 per row covers both 8-k sub-steps
        uint4 afr[4][2];
        uint4 bfr[4];
        const unsigned* Ab = As[buf];
        const unsigned* Bb = Bs[buf];
#pragma unroll
        for (int mt = 0; mt < 4; mt++) {
            const int m = wm + mt * 16 + gid;
            const int m8 = m + 8;
            afr[mt][0] = *(const uint4*)(Ab + m * 16 +
                                         (((tig + m + (m >> 2)) & 3) << 2));
            afr[mt][1] = *(const uint4*)(Ab + m8 * 16 +
                                         (((tig + m8 + (m8 >> 2)) & 3) << 2));
        }
#pragma unroll
        for (int nt = 0; nt < 4; nt++) {
            const int n = wn + nt * 8 + gid;
            bfr[nt] = *(const uint4*)(Bb + n * 16 +
                                      (((tig + n + (n >> 2)) & 3) << 2));
        }

        // kk = 0: components .x (k=tig), .y (k=tig+4)
#pragma unroll
        for (int mt = 0; mt < 4; mt++) {
            unsigned a[4] = {afr[mt][0].x, afr[mt][1].x,
                             afr[mt][0].y, afr[mt][1].y};
#pragma unroll
            for (int nt = 0; nt < 4; nt++) {
                unsigned b[2] = {bfr[nt].x, bfr[nt].y};
                mma8(acc[mt][nt], a, b);
            }
        }
        // kk = 1: components .z (k=tig+8), .w (k=tig+12)
#pragma unroll
        for (int mt = 0; mt < 4; mt++) {
            unsigned a[4] = {afr[mt][0].z, afr[mt][1].z,
                             afr[mt][0].w, afr[mt][1].w};
#pragma unroll
            for (int nt = 0; nt < 4; nt++) {
                unsigned b[2] = {bfr[nt].z, bfr[nt].w};
                mma8(acc[mt][nt], a, b);
            }
        }

        if (ch + 1 < 64) store_chunk(buf ^ 1);
    }

#pragma unroll
    for (int mt = 0; mt < 4; mt++) {
        int r = m0 + wm + mt * 16 + gid;
#pragma unroll
        for (int nt = 0; nt < 4; nt++) {
            int c = n0 + wn + nt * 8 + tig * 2;
            float b0v = bias ? bias[c] : 0.0f;
            float b1v = bias ? bias[c + 1] : 0.0f;
            float2 v0, v1;
            v0.x = acc[mt][nt][0] + b0v;
            v0.y = acc[mt][nt][1] + b1v;
            v1.x = acc[mt][nt][2] + b0v;
            v1.y = acc[mt][nt][3] + b1v;
            *(float2*)(Cout + (size_t)r * Cv + c) = v0;
            *(float2*)(Cout + (size_t)(r + 8) * Cv + c) = v1;
        }
    }
}

// ---------------------------------------------------------------------------
// RoPE (in-place on q and k, token-major [Mrows,1024] layout).
// ---------------------------------------------------------------------------
__global__ __launch_bounds__(256) void rope_kernel(
    const float* __restrict__ fcos, const float* __restrict__ fsin)
{
    const long total = (long)Mrows * 512;
    long gid = (long)blockIdx.x * blockDim.x + threadIdx.x;
    if (gid >= 2 * total) return;
    float* arr = (gid < total) ? g_q : g_k;
    long id = (gid < total) ? gid : (gid - total);

    int m = (int)(id / 512);
    int p = (int)(id % 512);
    int col = p * 2;
    int d = col & 63;
    int s = m % TNv;

    float c0 = fcos[(size_t)s * HDv + d];
    float c1 = fcos[(size_t)s * HDv + d + 1];
    float s0 = fsin[(size_t)s * HDv + d];
    float s1 = fsin[(size_t)s * HDv + d + 1];

    float2 x = *(float2*)(arr + (size_t)m * Cv + col);
    float2 y;
    y.x = x.x * c0 - x.y * s0;
    y.y = x.y * c1 + x.x * s1;
    *(float2*)(arr + (size_t)m * Cv + col) = y;
}

// ---------------------------------------------------------------------------
// Flash attention with tf32 mma.sync (unchanged from round 3, proven).
// ---------------------------------------------------------------------------
#define QS_OFF 0
#define KS_OFF 4608
#define VS_OFF 9216
#define PS_OFF 13824
#define RED_OFF 18432
#define MR_OFF 18688
#define LR_OFF 18752
#define AR_OFF 18816
#define ATTN_SMEM_WORDS 18880

__global__ __launch_bounds__(256) void attn_mma()
{
    extern __shared__ unsigned usm[];
    unsigned* Qs = usm + QS_OFF;
    unsigned* Ks = usm + KS_OFF;
    unsigned* Vs = usm + VS_OFF;
    unsigned* Ps = usm + PS_OFF;
    float* red  = (float*)(usm + RED_OFF);
    float* Mrow = (float*)(usm + MR_OFF);
    float* Lrow = (float*)(usm + LR_OFF);
    float* Arow = (float*)(usm + AR_OFF);

    const int bx = blockIdx.x;
    const int nb = bx % 9;
    const int tt = (bx / 9) % Tv;
    const int hh = (bx / (9 * Tv)) % Hv;
    const int b  = bx / (9 * Tv * Hv);
    const int tprev = (tt == 0) ? 1 : tt - 1;
    const int tnext = (tt == Tv - 1) ? Tv - 2 : tt + 1;

    const int t = threadIdx.x;
    const int lane = t & 31;
    const int w = t >> 5;
    const int gid = lane >> 2, tig = lane & 3;
    const int wm = w >> 2, wn = w & 3;
    const int lrow = t >> 2;
    const int dc = (t & 3) * 16;
    const int cstL = (t & 3) << 3;

    {
        const float* qb =
            g_q + (size_t)(b * TNv + tt * Nv + nb * 64 + lrow) * Cv + hh * HDv + dc;
#pragma unroll
        for (int j = 0; j < 4; j++) {
            float4 v = *(const float4*)(qb + 4 * j);
            int d0 = dc + 4 * j;
            int cq = lrow ^ cstL;
            Qs[(d0 + 0) * 72 + cq] = tf32r(v.x * 0.125f);
            Qs[(d0 + 1) * 72 + cq] = tf32r(v.y * 0.125f);
            Qs[(d0 + 2) * 72 + cq] = tf32r(v.z * 0.125f);
            Qs[(d0 + 3) * 72 + cq] = tf32r(v.w * 0.125f);
        }
    }
    if (t < 64) { Mrow[t] = -1e30f; Lrow[t] = 0.0f; }

    float o[2][2][4];
#pragma unroll
    for (int mi = 0; mi < 2; mi++)
#pragma unroll
        for (int nj = 0; nj < 2; nj++)
#pragma unroll
            for (int r = 0; r < 4; r++) o[mi][nj][r] = 0.0f;

    for (int kt = 0; kt < 18; kt++) {
        const int tsrc = (kt < 9) ? tprev : tnext;
        const int nk0 = (kt % 9) * 64;
        const size_t tok = (size_t)(b * TNv + tsrc * Nv + nk0 + lrow);
        const float* kb_ = g_k + tok * Cv + hh * HDv + dc;
        const float* vb_ = g_v + tok * Cv + hh * HDv + dc;

        __syncthreads();
#pragma unroll
        for (int j = 0; j < 4; j++) {
            float4 kv = *(const float4*)(kb_ + 4 * j);
            float4 vv = *(const float4*)(vb_ + 4 * j);
            int d0 = dc + 4 * j;
            int ck = lrow ^ cstL;
            Ks[(d0 + 0) * 72 + ck] = tf32r(kv.x);
            Ks[(d0 + 1) * 72 + ck] = tf32r(kv.y);
            Ks[(d0 + 2) * 72 + ck] = tf32r(kv.z);
            Ks[(d0 + 3) * 72 + ck] = tf32r(kv.w);
            uint4 pv;
            pv.x = tf32r(vv.x); pv.y = tf32r(vv.y);
            pv.z = tf32r(vv.z); pv.w = tf32r(vv.w);
            *(uint4*)&Vs[lrow * 72 + d0] = pv;
        }
        __syncthreads();

        float s[2][2][4];
#pragma unroll
        for (int mi = 0; mi < 2; mi++)
#pragma unroll
            for (int ni = 0; ni < 2; ni++)
#pragma unroll
                for (int r = 0; r < 4; r++) s[mi][ni][r] = 0.0f;
#pragma unroll
        for (int kb = 0; kb < 64; kb += 8) {
            const int cs = ((kb >> 4) & 3) << 3;
            const int kr0 = (kb + tig) * 72;
            const int kr1 = (kb + tig + 4) * 72;
            unsigned a[2][4], bb[2][2];
#pragma unroll
            for (int mi = 0; mi < 2; mi++) {
                int q0 = wm * 32 + mi * 16 + gid;
                a[mi][0] = Qs[kr0 + (q0 ^ cs)];
                a[mi][1] = Qs[kr0 + ((q0 + 8) ^ cs)];
                a[mi][2] = Qs[kr1 + (q0 ^ cs)];
                a[mi][3] = Qs[kr1 + ((q0 + 8) ^ cs)];
            }
#pragma unroll
            for (int ni = 0; ni < 2; ni++) {
                int kc = wn * 16 + ni * 8 + gid;
                bb[ni][0] = Ks[kr0 + (kc ^ cs)];
                bb[ni][1] = Ks[kr1 + (kc ^ cs)];
            }
#pragma unroll
            for (int mi = 0; mi < 2; mi++)
#pragma unroll
                for (int ni = 0; ni < 2; ni++)
                    mma8(s[mi][ni], a[mi], bb[ni]);
        }

#pragma unroll
        for (int mi = 0; mi < 2; mi++)
#pragma unroll
            for (int h2 = 0; h2 < 2; h2++) {
                float mx = fmaxf(fmaxf(s[mi][0][h2 * 2], s[mi][0][h2 * 2 + 1]),
                                 fmaxf(s[mi][1][h2 * 2], s[mi][1][h2 * 2 + 1]));
                mx = fmaxf(mx, __shfl_xor_sync(0xffffffffu, mx, 1));
                mx = fmaxf(mx, __shfl_xor_sync(0xffffffffu, mx, 2));
                if (tig == 0)
                    red[wn * 64 + wm * 32 + mi * 16 + h2 * 8 + gid] = mx;
            }
        __syncthreads();
        if (t < 64) {
            float tm = fmaxf(fmaxf(red[t], red[64 + t]),
                             fmaxf(red[128 + t], red[192 + t]));
            float mold = Mrow[t];
            float mnew = fmaxf(mold, tm);
            Mrow[t] = mnew;
            Arow[t] = __expf(mold - mnew);
        }
        __syncthreads();

        const int cp = wn << 3;
        const int k0c = wn * 16 + tig * 2;
#pragma unroll
        for (int mi = 0; mi < 2; mi++)
#pragma unroll
            for (int h2 = 0; h2 < 2; h2++) {
                int r = wm * 32 + mi * 16 + h2 * 8 + gid;
                float mrow = Mrow[r];
                float al = Arow[r];
                float p0 = __expf(s[mi][0][h2 * 2]     - mrow);
                float p1 = __expf(s[mi][0][h2 * 2 + 1] - mrow);
                float p2 = __expf(s[mi][1][h2 * 2]     - mrow);
                float p3 = __expf(s[mi][1][h2 * 2 + 1] - mrow);
                float rs = p0 + p1 + p2 + p3;
                rs += __shfl_xor_sync(0xffffffffu, rs, 1);
                rs += __shfl_xor_sync(0xffffffffu, rs, 2);
                if (tig == 0) red[wn * 64 + r] = rs;
                int rq = r ^ cp;
                Ps[(k0c + 0) * 72 + rq] = tf32r(p0);
                Ps[(k0c + 1) * 72 + rq] = tf32r(p1);
                Ps[(k0c + 8) * 72 + rq] = tf32r(p2);
                Ps[(k0c + 9) * 72 + rq] = tf32r(p3);
                o[mi][0][h2 * 2]     *= al;
                o[mi][0][h2 * 2 + 1] *= al;
                o[mi][1][h2 * 2]     *= al;
                o[mi][1][h2 * 2 + 1] *= al;
            }
        __syncthreads();
        if (t < 64)
            Lrow[t] = Lrow[t] * Arow[t] +
                      red[t] + red[64 + t] + red[128 + t] + red[192 + t];

#pragma unroll
        for (int kb = 0; kb < 64; kb += 8) {
            const int cs = ((kb >> 4) & 3) << 3;
            const int kr0 = (kb + tig) * 72;
            const int kr1 = (kb + tig + 4) * 72;
            unsigned a[2][4], bb[2][2];
#pragma unroll
            for (int mi = 0; mi < 2; mi++) {
                int q0 = wm * 32 + mi * 16 + gid;
                a[mi][0] = Ps[kr0 + (q0 ^ cs)];
                a[mi][1] = Ps[kr0 + ((q0 + 8) ^ cs)];
                a[mi][2] = Ps[kr1 + (q0 ^ cs)];
                a[mi][3] = Ps[kr1 + ((q0 + 8) ^ cs)];
            }
#pragma unroll
            for (int nj = 0; nj < 2; nj++) {
                int dcol = wn * 16 + nj * 8 + gid;
                bb[nj][0] = Vs[kr0 + dcol];
                bb[nj][1] = Vs[kr1 + dcol];
            }
#pragma unroll
            for (int mi = 0; mi < 2; mi++)
#pragma unroll
                for (int nj = 0; nj < 2; nj++)
                    mma8(o[mi][nj], a[mi], bb[nj]);
        }
    }

    __syncthreads();
#pragma unroll
    for (int mi = 0; mi < 2; mi++)
#pragma unroll
        for (int h2 = 0; h2 < 2; h2++) {
            int r = wm * 32 + mi * 16 + h2 * 8 + gid;
            float inv = 1.0f / Lrow[r];
            size_t token = (size_t)(b * TNv + tt * Nv + nb * 64 + r);
            float* ob = g_o + token * Cv + hh * HDv;
#pragma unroll
            for (int nj = 0; nj < 2; nj++) {
                int dcol = wn * 16 + nj * 8 + tig * 2;
                float2 v2;
                v2.x = o[mi][nj][h2 * 2] * inv;
                v2.y = o[mi][nj][h2 * 2 + 1] * inv;
                *(float2*)(ob + dcol) = v2;
            }
        }
}

// ---------------------------------------------------------------------------
// Launch
// ---------------------------------------------------------------------------
extern "C" void kernel_launch(void* const* d_in, const int* in_sizes, int n_in,
                              void* d_out, int out_size)
{
    (void)in_sizes; (void)n_in; (void)out_size;
    const float* img  = (const float*)d_in[0];
    const float* fcos = (const float*)d_in[1];
    const float* fsin = (const float*)d_in[2];
    const float* Wq   = (const float*)d_in[3];
    const float* Wk   = (const float*)d_in[4];
    const float* Wv   = (const float*)d_in[5];
    const float* Wo   = (const float*)d_in[6];
    const float* bo   = (const float*)d_in[7];
    float* out = (float*)d_out;

    float *q, *k, *v, *o;
    cudaGetSymbolAddress((void**)&q, g_q);
    cudaGetSymbolAddress((void**)&k, g_k);
    cudaGetSymbolAddress((void**)&v, g_v);
    cudaGetSymbolAddress((void**)&o, g_o);

    cudaFuncSetAttribute(attn_mma,
                         cudaFuncAttributeMaxDynamicSharedMemorySize,
                         ATTN_SMEM_WORDS * (int)sizeof(unsigned));

    dim3 gblk(256);
    dim3 ggrid(Cv / 128, Mrows / 128);   // (8, 72)

    gemm_tf32<<<ggrid, gblk>>>(img, Wq, q, nullptr);
    gemm_tf32<<<ggrid, gblk>>>(img, Wk, k, nullptr);
    gemm_tf32<<<ggrid, gblk>>>(img, Wv, v, nullptr);

    long pairs2 = 2L * Mrows * 512;
    int rblocks = (int)((pairs2 + 255) / 256);
    rope_kernel<<<rblocks, 256>>>(fcos, fsin);

    attn_mma<<<Bv * Hv * Tv * 9, 256,
               ATTN_SMEM_WORDS * sizeof(unsigned)>>>();

    gemm_tf32<<<ggrid, gblk>>>(o, Wo, out, bo);
}